// round 1
// baseline (speedup 1.0000x reference)
#include <cuda_runtime.h>
#include <math.h>

#define B_ 2
#define S_ 2048
#define E_ 768
#define H_ 8
#define D_ 96
#define M_ 4096   // B*S

// scratch (no cudaMalloc allowed)
__device__ float g_Q[M_ * E_];   // [B,H,S,D]
__device__ float g_K[M_ * E_];   // [B,H,S,D]  (also serves as V)
__device__ float g_AO[M_ * E_];  // attention output, [B,S,E]

// ---------------------------------------------------------------------------
// Projection GEMM: out = x @ W + b, scattered to [B,H,S,D].
// blockIdx.z: 0 -> (Wq,bq,g_Q), 1 -> (Wk,bk,g_K)
// 128x128 tile, BK=8, 256 threads, 8x8 micro-tile.
// ---------------------------------------------------------------------------
__global__ void __launch_bounds__(256) proj_kernel(
    const float* __restrict__ X,
    const float* __restrict__ Wq, const float* __restrict__ bq,
    const float* __restrict__ Wk, const float* __restrict__ bk)
{
    const float* W    = blockIdx.z ? Wk : Wq;
    const float* bias = blockIdx.z ? bk : bq;
    float* out        = blockIdx.z ? g_K : g_Q;

    __shared__ float As[8][128];   // transposed A tile
    __shared__ float Bs[8][128];

    const int tid  = threadIdx.x;
    const int m0   = blockIdx.x * 128;
    const int n0   = blockIdx.y * 128;
    const int arow = tid >> 1, acol = (tid & 1) * 4;
    const int brow = tid >> 5, bcol = (tid & 31) * 4;
    const int tx   = tid & 15, ty = tid >> 4;

    const float* Ap = X + (m0 + arow) * E_ + acol;
    const float* Wp = W + brow * E_ + n0 + bcol;

    float acc[8][8];
    #pragma unroll
    for (int i = 0; i < 8; i++)
        #pragma unroll
        for (int j = 0; j < 8; j++) acc[i][j] = 0.f;

    for (int k0 = 0; k0 < E_; k0 += 8) {
        float4 av = *(const float4*)Ap; Ap += 8;
        float4 bv = *(const float4*)Wp; Wp += 8 * E_;
        As[acol + 0][arow] = av.x;
        As[acol + 1][arow] = av.y;
        As[acol + 2][arow] = av.z;
        As[acol + 3][arow] = av.w;
        *(float4*)&Bs[brow][bcol] = bv;
        __syncthreads();
        #pragma unroll
        for (int kk = 0; kk < 8; kk++) {
            float a[8], b[8];
            *(float4*)(a)     = *(const float4*)&As[kk][ty * 8];
            *(float4*)(a + 4) = *(const float4*)&As[kk][ty * 8 + 4];
            *(float4*)(b)     = *(const float4*)&Bs[kk][tx * 8];
            *(float4*)(b + 4) = *(const float4*)&Bs[kk][tx * 8 + 4];
            #pragma unroll
            for (int i = 0; i < 8; i++)
                #pragma unroll
                for (int j = 0; j < 8; j++)
                    acc[i][j] = fmaf(a[i], b[j], acc[i][j]);
        }
        __syncthreads();
    }

    #pragma unroll
    for (int i = 0; i < 8; i++) {
        int m = m0 + ty * 8 + i;
        int bb = m >> 11, s = m & 2047;
        #pragma unroll
        for (int j = 0; j < 8; j++) {
            int n = n0 + tx * 8 + j;
            int h = n / D_, d = n % D_;
            out[(((bb << 3) + h) * S_ + s) * D_ + d] = acc[i][j] + bias[n];
        }
    }
}

// ---------------------------------------------------------------------------
// Output projection: Y = g_AO @ Wo + bo (plain row-major epilogue).
// ---------------------------------------------------------------------------
__global__ void __launch_bounds__(256) outproj_kernel(
    const float* __restrict__ Wo, const float* __restrict__ bo,
    float* __restrict__ Y)
{
    __shared__ float As[8][128];
    __shared__ float Bs[8][128];

    const int tid  = threadIdx.x;
    const int m0   = blockIdx.x * 128;
    const int n0   = blockIdx.y * 128;
    const int arow = tid >> 1, acol = (tid & 1) * 4;
    const int brow = tid >> 5, bcol = (tid & 31) * 4;
    const int tx   = tid & 15, ty = tid >> 4;

    const float* Ap = g_AO + (m0 + arow) * E_ + acol;
    const float* Wp = Wo + brow * E_ + n0 + bcol;

    float acc[8][8];
    #pragma unroll
    for (int i = 0; i < 8; i++)
        #pragma unroll
        for (int j = 0; j < 8; j++) acc[i][j] = 0.f;

    for (int k0 = 0; k0 < E_; k0 += 8) {
        float4 av = *(const float4*)Ap; Ap += 8;
        float4 bv = *(const float4*)Wp; Wp += 8 * E_;
        As[acol + 0][arow] = av.x;
        As[acol + 1][arow] = av.y;
        As[acol + 2][arow] = av.z;
        As[acol + 3][arow] = av.w;
        *(float4*)&Bs[brow][bcol] = bv;
        __syncthreads();
        #pragma unroll
        for (int kk = 0; kk < 8; kk++) {
            float a[8], b[8];
            *(float4*)(a)     = *(const float4*)&As[kk][ty * 8];
            *(float4*)(a + 4) = *(const float4*)&As[kk][ty * 8 + 4];
            *(float4*)(b)     = *(const float4*)&Bs[kk][tx * 8];
            *(float4*)(b + 4) = *(const float4*)&Bs[kk][tx * 8 + 4];
            #pragma unroll
            for (int i = 0; i < 8; i++)
                #pragma unroll
                for (int j = 0; j < 8; j++)
                    acc[i][j] = fmaf(a[i], b[j], acc[i][j]);
        }
        __syncthreads();
    }

    #pragma unroll
    for (int i = 0; i < 8; i++) {
        int m = m0 + ty * 8 + i;
        #pragma unroll
        for (int j = 0; j < 8; j++) {
            int n = n0 + tx * 8 + j;
            Y[m * E_ + n] = acc[i][j] + bo[n];
        }
    }
}

// ---------------------------------------------------------------------------
// Flash attention, V == K (faithful to reference bug).
// SCALING is applied to the OUTPUT (softmax-then-scale == scale-output).
// CTA: 64 query rows; loop over 32 key tiles of 64.
// Tiles live in smem rows padded to 128 floats with float4 XOR swizzle
// (slot = d4 ^ (row&7)) -> conflict-free for both QK^T and PV reads.
// ---------------------------------------------------------------------------
#define ATTN_SMEM_BYTES ((64 * 128 * 2 + 64 * 68) * 4)   // 82944

__global__ void __launch_bounds__(256, 2) attn_kernel()
{
    extern __shared__ float sm[];
    float* qs = sm;                  // [64][128] swizzled
    float* ks = sm + 64 * 128;       // [64][128] swizzled (K and V)
    float* ps = sm + 2 * 64 * 128;   // [64][68]

    const int tid = threadIdx.x;
    const int tx  = tid & 15, ty = tid >> 4;
    const int bh  = blockIdx.y;      // 0..15  (b*8+h)
    const int qt  = blockIdx.x;      // 0..31

    const float* Qg = g_Q + (size_t)bh * (S_ * D_) + qt * 64 * D_;
    const float* Kg = g_K + (size_t)bh * (S_ * D_);

    // load Q tile (64 rows x 24 float4)
    #pragma unroll
    for (int it = 0; it < 6; it++) {
        int idx = tid + it * 256;           // < 1536
        int r = idx / 24, c4 = idx % 24;
        float4 v = *(const float4*)(Qg + r * D_ + c4 * 4);
        *(float4*)(qs + r * 128 + 4 * (c4 ^ (r & 7))) = v;
    }

    float O[4][6];
    #pragma unroll
    for (int i = 0; i < 4; i++)
        #pragma unroll
        for (int jc = 0; jc < 6; jc++) O[i][jc] = 0.f;
    float mrow[4] = {-1e30f, -1e30f, -1e30f, -1e30f};
    float lrow[4] = {0.f, 0.f, 0.f, 0.f};

    int dcol[6];
    #pragma unroll
    for (int jc = 0; jc < 6; jc++) dcol[jc] = tx + 16 * jc;

    const int qsl = ty & 7;
    const int ksl = tx & 7;
    const float4* q4 = (const float4*)qs;
    const float4* k4 = (const float4*)ks;

    for (int kt = 0; kt < 32; kt++) {
        __syncthreads();   // previous tile fully consumed
        // load K tile kt
        #pragma unroll
        for (int it = 0; it < 6; it++) {
            int idx = tid + it * 256;
            int r = idx / 24, c4 = idx % 24;
            float4 v = *(const float4*)(Kg + (kt * 64 + r) * D_ + c4 * 4);
            *(float4*)(ks + r * 128 + 4 * (c4 ^ (r & 7))) = v;
        }
        __syncthreads();

        // S = Q K^T  (each thread: rows ty+16i, cols tx+16j)
        float acc[4][4];
        #pragma unroll
        for (int i = 0; i < 4; i++)
            #pragma unroll
            for (int j = 0; j < 4; j++) acc[i][j] = 0.f;

        #pragma unroll 4
        for (int d4 = 0; d4 < 24; d4++) {
            float4 qv[4], kv[4];
            #pragma unroll
            for (int i = 0; i < 4; i++)
                qv[i] = q4[(ty + 16 * i) * 32 + (d4 ^ qsl)];
            #pragma unroll
            for (int j = 0; j < 4; j++)
                kv[j] = k4[(tx + 16 * j) * 32 + (d4 ^ ksl)];
            #pragma unroll
            for (int i = 0; i < 4; i++)
                #pragma unroll
                for (int j = 0; j < 4; j++) {
                    acc[i][j] = fmaf(qv[i].x, kv[j].x, acc[i][j]);
                    acc[i][j] = fmaf(qv[i].y, kv[j].y, acc[i][j]);
                    acc[i][j] = fmaf(qv[i].z, kv[j].z, acc[i][j]);
                    acc[i][j] = fmaf(qv[i].w, kv[j].w, acc[i][j]);
                }
        }

        // online softmax per row (reduction across the 16 tx lanes)
        #pragma unroll
        for (int i = 0; i < 4; i++) {
            float mloc = fmaxf(fmaxf(acc[i][0], acc[i][1]),
                               fmaxf(acc[i][2], acc[i][3]));
            #pragma unroll
            for (int o = 8; o > 0; o >>= 1)
                mloc = fmaxf(mloc, __shfl_xor_sync(0xffffffffu, mloc, o));
            float mnew  = fmaxf(mrow[i], mloc);
            float alpha = __expf(mrow[i] - mnew);
            mrow[i] = mnew;
            float p[4], sloc = 0.f;
            #pragma unroll
            for (int j = 0; j < 4; j++) {
                p[j] = __expf(acc[i][j] - mnew);
                sloc += p[j];
            }
            #pragma unroll
            for (int o = 8; o > 0; o >>= 1)
                sloc += __shfl_xor_sync(0xffffffffu, sloc, o);
            lrow[i] = lrow[i] * alpha + sloc;
            #pragma unroll
            for (int jc = 0; jc < 6; jc++) O[i][jc] *= alpha;
            #pragma unroll
            for (int j = 0; j < 4; j++)
                ps[(ty + 16 * i) * 68 + tx + 16 * j] = p[j];
        }
        __syncthreads();

        // O += P @ V   (V == K tile in ks)
        #pragma unroll 2
        for (int j2 = 0; j2 < 64; j2++) {
            float pv[4];
            #pragma unroll
            for (int i = 0; i < 4; i++)
                pv[i] = ps[(ty + 16 * i) * 68 + j2];
            const int cofs = (j2 & 7) << 2;
            const float* vrow = ks + j2 * 128;
            float vv[6];
            #pragma unroll
            for (int jc = 0; jc < 6; jc++)
                vv[jc] = vrow[dcol[jc] ^ cofs];
            #pragma unroll
            for (int i = 0; i < 4; i++)
                #pragma unroll
                for (int jc = 0; jc < 6; jc++)
                    O[i][jc] = fmaf(pv[i], vv[jc], O[i][jc]);
        }
    }

    // epilogue: O/l * SCALING, write to [B,S,E]
    const float SCALE = 0.10206207261596577f;   // 96^-0.5
    const int bb = bh >> 3, h = bh & 7;
    #pragma unroll
    for (int i = 0; i < 4; i++) {
        int srow = qt * 64 + ty + 16 * i;
        float inv = SCALE / lrow[i];
        float* dst = g_AO + ((size_t)(bb * S_ + srow)) * E_ + h * D_;
        #pragma unroll
        for (int jc = 0; jc < 6; jc++)
            dst[dcol[jc]] = O[i][jc] * inv;
    }
}

// ---------------------------------------------------------------------------
extern "C" void kernel_launch(void* const* d_in, const int* in_sizes, int n_in,
                              void* d_out, int out_size)
{
    const float* x  = (const float*)d_in[0];
    const float* Wq = (const float*)d_in[1];
    const float* bq = (const float*)d_in[2];
    const float* Wk = (const float*)d_in[3];
    const float* bk = (const float*)d_in[4];
    const float* Wo = (const float*)d_in[5];
    const float* bo = (const float*)d_in[6];
    float* out = (float*)d_out;

    cudaFuncSetAttribute(attn_kernel,
                         cudaFuncAttributeMaxDynamicSharedMemorySize,
                         ATTN_SMEM_BYTES);

    proj_kernel<<<dim3(32, 6, 2), 256>>>(x, Wq, bq, Wk, bk);
    attn_kernel<<<dim3(32, 16), 256, ATTN_SMEM_BYTES>>>();
    outproj_kernel<<<dim3(32, 6), 256>>>(Wo, bo, out);
}